// round 2
// baseline (speedup 1.0000x reference)
#include <cuda_runtime.h>
#include <math.h>
#include <stdint.h>

#define Bdim 128
#define Hdim 512
#define Ldim 256
#define OUTdim 256
#define NCTA 128
#define NTHR 256

// ---------------- scratch state (k-major: [feature][batch]) ----------------
__device__ __align__(128) float g_xhatT [Hdim*Bdim];   // x_hat for current step (GEMM A rows 0..511)
__device__ __align__(128) float g_hsT   [Hdim*Bdim];   // h_scaled = gamma_h * h_prev
__device__ __align__(128) float g_deltaT[Hdim*Bdim];
__device__ __align__(128) float g_hT    [Hdim*Bdim];
__device__ __align__(128) float g_xlastT[Hdim*Bdim];
__device__ __align__(128) float g_xmeanT[Hdim*Bdim];
__device__ __align__(128) float g_zT    [Hdim*Bdim];
__device__ __align__(128) float g_rhT   [Hdim*Bdim];
__device__ __align__(128) float g_pre3T [Hdim*Bdim];
__device__ __align__(128) float g_miT   [(size_t)Ldim*Hdim*Bdim]; // 64MB: mask as float, [i*H+h][b]
__device__ __align__(128) float g_dtT   [Ldim*Bdim];
__device__ __align__(128) float g_hseq  [(size_t)Ldim*Hdim*Bdim]; // 64MB: [i][h][b]
__device__ unsigned g_bar_count;
__device__ unsigned g_bar_epoch;

// ---------------- grid barrier (all 128 CTAs guaranteed co-resident) -------
__device__ __forceinline__ void grid_barrier(unsigned &epoch) {
    __threadfence();        // release all prior global writes (executed by every thread)
    __syncthreads();
    if (threadIdx.x == 0) {
        unsigned old = atomicAdd(&g_bar_count, 1);
        if (old == gridDim.x - 1) {
            g_bar_count = 0;
            __threadfence();
            atomicAdd(&g_bar_epoch, 1);
        } else {
            while (*(volatile unsigned*)&g_bar_epoch == epoch) { __nanosleep(32); }
        }
    }
    epoch++;
    __syncthreads();
}

// ---------------- generic skinny-GEMM accumulate ----------------------------
// A: k-major activation [k][128] in global. W: SMEM slice [k][wstride].
// Each thread: 4 consecutive batch rows (b0..b0+3) x NJ cols starting at jc.
template<int NJ, int K, bool CG>
__device__ __forceinline__ void gemm_acc(const float* __restrict__ A,
                                         const float* __restrict__ W,
                                         int wstride, int jc, int b0,
                                         float (&acc)[NJ][4]) {
#pragma unroll 4
    for (int k = 0; k < K; k++) {
        float4 a4;
        const float4* p = reinterpret_cast<const float4*>(A + (size_t)k*Bdim + b0);
        if constexpr (CG) a4 = __ldcg(p); else a4 = __ldg(p);
#pragma unroll
        for (int j = 0; j < NJ; j++) {
            float w = W[k*wstride + jc + j];
            acc[j][0] = fmaf(a4.x, w, acc[j][0]);
            acc[j][1] = fmaf(a4.y, w, acc[j][1]);
            acc[j][2] = fmaf(a4.z, w, acc[j][2]);
            acc[j][3] = fmaf(a4.w, w, acc[j][3]);
        }
    }
}

// ---------------- setup: mask transpose (to [i*H+h][b] float) ---------------
__global__ void k_transpose_mask(const int* __restrict__ mask) {
    __shared__ float tile[32][33];
    int ij0 = blockIdx.x * 32;       // over L*H = 131072
    int b0  = blockIdx.y * 32;       // over B = 128
    int tx = threadIdx.x, ty = threadIdx.y;
    for (int r = ty; r < 32; r += 8)
        tile[r][tx] = (float)mask[(size_t)(b0 + r)*(Ldim*Hdim) + ij0 + tx];
    __syncthreads();
    for (int r = ty; r < 32; r += 8)
        g_miT[(size_t)(ij0 + r)*Bdim + b0 + tx] = tile[tx][r];
}

// ---------------- setup: x_mean, dt, state init ------------------------------
__global__ void k_setup(const float* __restrict__ C, const float* __restrict__ t,
                        const int* __restrict__ mask) {
    int b = blockIdx.x;
    int h = threadIdx.x;     // 512 threads
    float s1 = 0.f, s0 = 0.f;
    for (int i = 0; i < Ldim; i++) {
        float m = (float)mask[((size_t)b*Ldim + i)*Hdim + h];
        s1 += m * C[i*Hdim + h];
        s0 += m;
    }
    float xm = s1 / fmaxf(s0, 1.f);
    int idx = h*Bdim + b;
    g_xmeanT[idx] = xm;
    g_xlastT[idx] = xm;
    g_hT[idx]     = 0.f;
    g_deltaT[idx] = 0.f;
    float m0 = (float)mask[((size_t)b*Ldim)*Hdim + h];
    // step-0 x_hat: x_last==x_mean makes gamma_x cancel out
    g_xhatT[idx] = m0 * C[h] + (1.f - m0) * xm;
    if (h < Ldim) {
        int i = h;
        g_dtT[i*Bdim + b] = (i == 0) ? 0.f : (t[b*Ldim + i] - t[b*Ldim + i - 1]);
    }
    if (b == 0 && h == 0) { g_bar_count = 0; g_bar_epoch = 0; }
}

// ---------------- persistent main recurrence kernel --------------------------
// CTA c owns: G1 cols {c+128*j : j=0..11} of the 1536-wide [Wx;Wm;Wh_zr] space
//             (j<8 -> zr region incl. Wh; j>=8 -> candidate region, no Wh)
//             and h-cols {4c..4c+3} for W_gh / Wh3 / elementwise.
// SMEM floats: sWx 6144 | sWm 6144 | sWhzr 4096 | sWgh 2048 | sWh3 2048 | sPart 1536 | sRed 1536
#define SMEM_FLOATS 23552
__global__ void __launch_bounds__(NTHR, 1) k_main(
    const float* __restrict__ C,   const float* __restrict__ Wx,
    const float* __restrict__ Wh,  const float* __restrict__ Wm,
    const float* __restrict__ bvec,const float* __restrict__ w_gx,
    const float* __restrict__ b_gx,const float* __restrict__ Wgh,
    const float* __restrict__ b_gh)
{
    extern __shared__ float sm[];
    float* sWx   = sm;
    float* sWm   = sm + 6144;
    float* sWhzr = sm + 12288;
    float* sWgh  = sm + 16384;
    float* sWh3  = sm + 18432;
    float* sPart = sm + 20480;
    float* sRed  = sm + 22016;

    const int c   = blockIdx.x;
    const int tid = threadIdx.x;

    // one-time weight slice load (strided gather; amortized over 256 steps)
    for (int idx = tid; idx < 6144; idx += NTHR) {
        int k = idx / 12, j = idx % 12;
        sWx[idx] = Wx[k*1536 + c + 128*j];
        sWm[idx] = Wm[k*1536 + c + 128*j];
    }
    for (int idx = tid; idx < 4096; idx += NTHR) {
        int k = idx / 8, j = idx % 8;
        sWhzr[idx] = Wh[k*1536 + c + 128*j];
    }
    for (int idx = tid; idx < 2048; idx += NTHR) {
        int k = idx / 4, j = idx % 4;
        sWgh[idx] = Wgh[k*512 + 4*c + j];
        sWh3[idx] = Wh[k*1536 + 1024 + 4*c + j];
    }
    __syncthreads();

    const int g  = tid >> 7;          // k-group / matrix-group (0,1)
    const int lt = tid & 127;
    const int rq = lt & 31;
    const int b0 = rq * 4;            // 4 consecutive batch rows
    const int qt = lt >> 5;           // 0..3 column sub-group
    unsigned epoch = 0;

    for (int i = 0; i < Ldim; i++) {
        // ================= Phase P =================
        // P2: partial(12 cols) = x_hat @ Wx  (g==0)  +  mi @ Wm  (g==1)
        {
            float acc[3][4] = {};
            if (g == 0)
                gemm_acc<3,512,true >(g_xhatT, sWx, 12, qt*3, b0, acc);
            else
                gemm_acc<3,512,false>(g_miT + (size_t)i*Hdim*Bdim, sWm, 12, qt*3, b0, acc);
            if (g == 1) {
#pragma unroll
                for (int j = 0; j < 3; j++)
#pragma unroll
                    for (int r2 = 0; r2 < 4; r2++)
                        sRed[(qt*3 + j)*Bdim + b0 + r2] = acc[j][r2];
            }
            __syncthreads();
            if (g == 0) {
#pragma unroll
                for (int j = 0; j < 3; j++) {
                    int jj  = qt*3 + j;
                    int col = c + 128*jj;
                    float bb = __ldg(&bvec[col]);
#pragma unroll
                    for (int r2 = 0; r2 < 4; r2++) {
                        float s = acc[j][r2] + sRed[jj*Bdim + b0 + r2];
                        sPart[jj*Bdim + b0 + r2] = s;
                        if (jj >= 8)   // candidate pre-activation is final now
                            g_pre3T[(col - 1024)*Bdim + b0 + r2] = s + bb;
                    }
                }
            }
            __syncthreads();
        }
        // P1: gamma_h = exp(-relu(delta @ W_gh + b_gh)); h_scaled = gamma_h * h
        {
            float acc[1][4] = {};
            gemm_acc<1,256,true>(g_deltaT + (size_t)(g*256)*Bdim,
                                 sWgh + (g*256)*4, 4, qt, b0, acc);
            if (g == 1) {
#pragma unroll
                for (int r2 = 0; r2 < 4; r2++)
                    sRed[qt*Bdim + b0 + r2] = acc[0][r2];
            }
            __syncthreads();
            if (g == 0) {
                int col = 4*c + qt;
                float bgh = __ldg(&b_gh[col]);
#pragma unroll
                for (int r2 = 0; r2 < 4; r2++) {
                    float s   = acc[0][r2] + sRed[qt*Bdim + b0 + r2] + bgh;
                    float gam = __expf(-fmaxf(0.f, s));
                    float hp  = __ldcg(&g_hT[col*Bdim + b0 + r2]);
                    g_hsT[col*Bdim + b0 + r2] = gam * hp;
                }
            }
        }
        grid_barrier(epoch);

        // ================= Phase Q =================
        // zr = sigmoid(partial + h_scaled @ Wh[:, :2H] + b)
        {
            float acc[2][4] = {};
            gemm_acc<2,256,true>(g_hsT + (size_t)(g*256)*Bdim,
                                 sWhzr + (g*256)*8, 8, qt*2, b0, acc);
            if (g == 1) {
#pragma unroll
                for (int j = 0; j < 2; j++)
#pragma unroll
                    for (int r2 = 0; r2 < 4; r2++)
                        sRed[(qt*2 + j)*Bdim + b0 + r2] = acc[j][r2];
            }
            __syncthreads();
            if (g == 0) {
#pragma unroll
                for (int j = 0; j < 2; j++) {
                    int jj  = qt*2 + j;
                    int col = c + 128*jj;
                    float bb = __ldg(&bvec[col]);
#pragma unroll
                    for (int r2 = 0; r2 < 4; r2++) {
                        int bi = b0 + r2;
                        float s  = acc[j][r2] + sRed[jj*Bdim + bi]
                                 + sPart[jj*Bdim + bi] + bb;
                        float sg = 1.f / (1.f + __expf(-s));
                        if (col < 512) {
                            g_zT[col*Bdim + bi] = sg;               // z
                        } else {
                            int hc = col - 512;                      // r -> r*h_scaled
                            g_rhT[hc*Bdim + bi] = sg * __ldcg(&g_hsT[hc*Bdim + bi]);
                        }
                    }
                }
            }
        }
        grid_barrier(epoch);

        // ================= Phase R =================
        // h_tilde = tanh(pre3 + rh @ Wh3); h_new = (1-z)*h_scaled + z*h_tilde
        // + fused elementwise prep of next step (delta, gamma_x, x_last, x_hat)
        {
            float acc[1][4] = {};
            gemm_acc<1,256,true>(g_rhT + (size_t)(g*256)*Bdim,
                                 sWh3 + (g*256)*4, 4, qt, b0, acc);
            if (g == 1) {
#pragma unroll
                for (int r2 = 0; r2 < 4; r2++)
                    sRed[qt*Bdim + b0 + r2] = acc[0][r2];
            }
            __syncthreads();
            if (g == 0) {
                int col = 4*c + qt;
                float wgx = __ldg(&w_gx[col]);
                float bgx = __ldg(&b_gx[col]);
                float xin  = __ldg(&C[i*Hdim + col]);
                float xin2 = (i + 1 < Ldim) ? __ldg(&C[(i+1)*Hdim + col]) : 0.f;
#pragma unroll
                for (int r2 = 0; r2 < 4; r2++) {
                    int bi  = b0 + r2;
                    int idx = col*Bdim + bi;
                    float s  = acc[0][r2] + sRed[qt*Bdim + bi];
                    float ht = tanhf(__ldcg(&g_pre3T[idx]) + s);
                    float z  = __ldcg(&g_zT[idx]);
                    float hs = __ldcg(&g_hsT[idx]);
                    float hn = (1.f - z)*hs + z*ht;
                    g_hT[idx] = hn;
                    g_hseq[((size_t)i*Hdim + col)*Bdim + bi] = hn;
                    if (i + 1 < Ldim) {
                        float mi   = __ldg(&g_miT[((size_t)i*Hdim + col)*Bdim + bi]);
                        float dold = __ldcg(&g_deltaT[idx]);
                        float dnew = __ldg(&g_dtT[(i+1)*Bdim + bi]) + (1.f - mi)*dold;
                        g_deltaT[idx] = dnew;
                        float gx = __expf(-fmaxf(0.f, wgx*dnew + bgx));
                        float xl = __ldcg(&g_xlastT[idx]);
                        float xln = mi*xin + (1.f - mi)*xl;
                        g_xlastT[idx] = xln;
                        float mi2 = __ldg(&g_miT[((size_t)(i+1)*Hdim + col)*Bdim + bi]);
                        float xm  = __ldg(&g_xmeanT[idx]);
                        g_xhatT[idx] = mi2*xin2 + (1.f - mi2)*(gx*xln + (1.f - gx)*xm);
                    }
                }
            }
        }
        grid_barrier(epoch);
    }
}

// ---------------- final output GEMM: out = h_seq @ W_out + b_out -------------
__global__ void __launch_bounds__(256) k_out(const float* __restrict__ Wout,
                                             const float* __restrict__ bout,
                                             float* __restrict__ out) {
    extern __shared__ float sW[];      // [512][64]
    int i  = blockIdx.x;               // sequence position
    int oy = blockIdx.y;               // 64-wide output-col tile
    int tid = threadIdx.x;
    for (int idx = tid; idx < 512*64; idx += 256) {
        int k = idx >> 6, o = idx & 63;
        sW[idx] = Wout[k*OUTdim + oy*64 + o];
    }
    __syncthreads();
    int rq = tid & 31;  int b0 = rq*4;
    int ot = tid >> 5;                 // 0..7 -> 8 output cols each
    float acc[4][8] = {};
    const float* A = g_hseq + (size_t)i*Hdim*Bdim;
#pragma unroll 2
    for (int k = 0; k < 512; k++) {
        float4 a4 = *reinterpret_cast<const float4*>(A + (size_t)k*Bdim + b0);
#pragma unroll
        for (int o = 0; o < 8; o++) {
            float w = sW[k*64 + ot*8 + o];
            acc[0][o] = fmaf(a4.x, w, acc[0][o]);
            acc[1][o] = fmaf(a4.y, w, acc[1][o]);
            acc[2][o] = fmaf(a4.z, w, acc[2][o]);
            acc[3][o] = fmaf(a4.w, w, acc[3][o]);
        }
    }
    int o0 = oy*64 + ot*8;
#pragma unroll
    for (int r2 = 0; r2 < 4; r2++) {
        int b = b0 + r2;
#pragma unroll
        for (int o = 0; o < 8; o++)
            out[((size_t)b*Ldim + i)*OUTdim + o0 + o] = acc[r2][o] + __ldg(&bout[o0 + o]);
    }
}

// ---------------- launch ------------------------------------------------------
extern "C" void kernel_launch(void* const* d_in, const int* in_sizes, int n_in,
                              void* d_out, int out_size) {
    const float* C    = (const float*)d_in[0];
    const float* t    = (const float*)d_in[1];
    const int*   mask = (const int*)  d_in[2];
    const float* Wx   = (const float*)d_in[3];
    const float* Wh   = (const float*)d_in[4];
    const float* Wm   = (const float*)d_in[5];
    const float* bvec = (const float*)d_in[6];
    const float* wgx  = (const float*)d_in[7];
    const float* bgx  = (const float*)d_in[8];
    const float* Wgh  = (const float*)d_in[9];
    const float* bgh  = (const float*)d_in[10];
    const float* Wout = (const float*)d_in[11];
    const float* bout = (const float*)d_in[12];
    float* out = (float*)d_out;

    cudaFuncSetAttribute(k_main, cudaFuncAttributeMaxDynamicSharedMemorySize,
                         SMEM_FLOATS * 4);
    cudaFuncSetAttribute(k_out, cudaFuncAttributeMaxDynamicSharedMemorySize,
                         512*64*4);

    dim3 tb(32, 8);
    dim3 tg((Ldim*Hdim)/32, Bdim/32);
    k_transpose_mask<<<tg, tb>>>(mask);
    k_setup<<<Bdim, Hdim>>>(C, t, mask);
    k_main<<<NCTA, NTHR, SMEM_FLOATS*4>>>(C, Wx, Wh, Wm, bvec, wgx, bgx, Wgh, bgh);
    k_out<<<dim3(Ldim, 4), 256, 512*64*4>>>(Wout, bout, out);
}

// round 3
// speedup vs baseline: 5.7347x; 5.7347x over previous
#include <cuda_runtime.h>
#include <math.h>
#include <stdint.h>

#define Bdim 128
#define Hdim 512
#define Ldim 256
#define OUTdim 256
#define NCTA 128

// ---------------- persistent state & precomputed sequences ------------------
__device__ __align__(128) float g_xmeanT[Hdim*Bdim];
__device__ __align__(128) float g_dtT   [Ldim*Bdim];
__device__ __align__(128) float g_hsT   [Hdim*Bdim];          // h_scaled (recurrent)
__device__ __align__(128) float g_zT    [Hdim*Bdim];
__device__ __align__(128) float g_rhT   [Hdim*Bdim];
__device__ __align__(128) float g_miT   [(size_t)Ldim*Hdim*Bdim];   // mask as float [i][h][b]
__device__ __align__(128) float g_xhatS [(size_t)Ldim*Hdim*Bdim];   // x_hat per step
__device__ __align__(128) float g_deltaS[(size_t)Ldim*Hdim*Bdim];   // delta per step
__device__ __align__(128) float g_preZ  [(size_t)Ldim*2*Hdim*Bdim]; // zr pre-activation (+bias)
__device__ __align__(128) float g_preC  [(size_t)Ldim*Hdim*Bdim];   // cand pre-activation (+bias)
__device__ __align__(128) float g_gamma [(size_t)Ldim*Hdim*Bdim];   // gamma_h per step
__device__ __align__(128) float g_hseq  [(size_t)Ldim*Hdim*Bdim];   // outputs of recurrence
__device__ unsigned g_bar_count;
__device__ unsigned g_bar_epoch;

// ---------------- cp.async helpers ------------------------------------------
__device__ __forceinline__ void cp16(void* s, const void* g) {
    unsigned sa = (unsigned)__cvta_generic_to_shared(s);
    asm volatile("cp.async.cg.shared.global [%0], [%1], 16;\n" :: "r"(sa), "l"(g));
}
#define CP_COMMIT asm volatile("cp.async.commit_group;\n" ::: "memory")
#define CP_WAIT1  asm volatile("cp.async.wait_group 1;\n" ::: "memory")
#define CP_WAIT0  asm volatile("cp.async.wait_group 0;\n" ::: "memory")

// ---------------- grid barrier (128 co-resident CTAs) -----------------------
__device__ __forceinline__ void grid_barrier(unsigned &epoch) {
    __threadfence();
    __syncthreads();
    if (threadIdx.x == 0) {
        unsigned old = atomicAdd(&g_bar_count, 1);
        if (old == gridDim.x - 1) {
            g_bar_count = 0;
            __threadfence();
            atomicAdd(&g_bar_epoch, 1);
        } else {
            while (*(volatile unsigned*)&g_bar_epoch == epoch) { __nanosleep(32); }
        }
    }
    epoch++;
    __syncthreads();
}

// ---------------- setup: mask transpose to [i*H+h][b] float -----------------
__global__ void k_transpose_mask(const int* __restrict__ mask) {
    __shared__ float tile[32][33];
    int ij0 = blockIdx.x * 32;
    int b0  = blockIdx.y * 32;
    int tx = threadIdx.x, ty = threadIdx.y;
    for (int r = ty; r < 32; r += 8)
        tile[r][tx] = (float)mask[(size_t)(b0 + r)*(Ldim*Hdim) + ij0 + tx];
    __syncthreads();
    for (int r = ty; r < 32; r += 8)
        g_miT[(size_t)(ij0 + r)*Bdim + b0 + tx] = tile[tx][r];
}

// ---------------- setup: x_mean, dt, barrier reset ---------------------------
__global__ void k_setup(const float* __restrict__ C, const float* __restrict__ t,
                        const int* __restrict__ mask) {
    int b = blockIdx.x;
    int h = threadIdx.x;                 // 512
    float s1 = 0.f, s0 = 0.f;
    for (int i = 0; i < Ldim; i++) {
        float m = (float)mask[((size_t)b*Ldim + i)*Hdim + h];
        s1 += m * C[i*Hdim + h];
        s0 += m;
    }
    g_xmeanT[h*Bdim + b] = s1 / fmaxf(s0, 1.f);
    if (h < Ldim) {
        int i = h;
        g_dtT[i*Bdim + b] = (i == 0) ? 0.f : (t[b*Ldim + i] - t[b*Ldim + i - 1]);
    }
    if (b == 0 && h == 0) { g_bar_count = 0; g_bar_epoch = 0; }
}

// ---------------- elementwise scan: delta[i], x_hat[i] for all i -------------
__global__ void __launch_bounds__(512) k_scan(const float* __restrict__ C,
                                              const float* __restrict__ w_gx,
                                              const float* __restrict__ b_gx) {
    int gid = blockIdx.x * 512 + threadIdx.x;   // 65536
    int h = gid >> 7, b = gid & 127;
    float xm = g_xmeanT[h*Bdim + b];
    float x_last = xm, delta = 0.f, m_prev = 1.f;
    float wg = __ldg(&w_gx[h]), bg = __ldg(&b_gx[h]);
    for (int i = 0; i < Ldim; i++) {
        float dti = g_dtT[i*Bdim + b];
        delta = dti + (1.f - m_prev) * delta;
        float m  = g_miT[((size_t)i*Hdim + h)*Bdim + b];
        float xi = __ldg(&C[i*Hdim + h]);
        float gx = __expf(-fmaxf(0.f, wg*delta + bg));
        size_t idx = (size_t)i*(Hdim*Bdim) + h*Bdim + b;
        g_xhatS[idx]  = m*xi + (1.f - m)*(gx*x_last + (1.f - gx)*xm);
        g_deltaS[idx] = delta;
        x_last = m*xi + (1.f - m)*x_last;
        m_prev = m;
    }
    g_hsT[h*Bdim + b] = 0.f;   // h_scaled init (h0 = 0)
}

// ---------------- precompute GEMM: pre = [xhat;m] @ [Wx;Wm] + b --------------
// grid (12, 256): x = 128-col tile, y = i. 256 thr, 128x128 out tile, K=1024.
__global__ void __launch_bounds__(256, 2) k_pre(const float* __restrict__ Wx,
                                                const float* __restrict__ Wm,
                                                const float* __restrict__ bvec) {
    extern __shared__ float sm[];
    float* sA = sm;          // [2][32][128]
    float* sW = sm + 8192;   // [2][32][128]
    int ct = blockIdx.x, i = blockIdx.y, tid = threadIdx.x;
    const float* Ax = g_xhatS + (size_t)i*(Hdim*Bdim);
    const float* Am = g_miT   + (size_t)i*(Hdim*Bdim);
    int bo = (tid & 15) * 8;
    int co = (tid >> 4) * 8;
    float acc[8][8] = {};

    auto load = [&](int ck, int buf) {
#pragma unroll
        for (int v = 0; v < 4; v++) {
            int idx = tid + v*256;          // float4 idx 0..1023
            int kk  = idx >> 5;
            int q   = (idx & 31) * 4;
            int k   = ck*32 + kk;
            const float* srcA = (k < Hdim ? Ax + (size_t)k*Bdim
                                          : Am + (size_t)(k-Hdim)*Bdim) + q;
            cp16(sA + buf*4096 + idx*4, srcA);
            const float* srcW = (k < Hdim ? Wx + (size_t)k*1536
                                          : Wm + (size_t)(k-Hdim)*1536) + ct*128 + q;
            cp16(sW + buf*4096 + idx*4, srcW);
        }
    };

    load(0, 0); CP_COMMIT;
    for (int ck = 0; ck < 32; ck++) {
        if (ck < 31) { load(ck+1, (ck+1)&1); CP_COMMIT; CP_WAIT1; } else { CP_WAIT0; }
        __syncthreads();
        const float* A = sA + (ck&1)*4096;
        const float* W = sW + (ck&1)*4096;
#pragma unroll 4
        for (int k = 0; k < 32; k++) {
            float4 a0 = *(const float4*)(A + k*128 + bo);
            float4 a1 = *(const float4*)(A + k*128 + bo + 4);
            float4 w0 = *(const float4*)(W + k*128 + co);
            float4 w1 = *(const float4*)(W + k*128 + co + 4);
            float av[8] = {a0.x,a0.y,a0.z,a0.w,a1.x,a1.y,a1.z,a1.w};
            float wv[8] = {w0.x,w0.y,w0.z,w0.w,w1.x,w1.y,w1.z,w1.w};
#pragma unroll
            for (int cc = 0; cc < 8; cc++)
#pragma unroll
                for (int bb = 0; bb < 8; bb++)
                    acc[cc][bb] = fmaf(av[bb], wv[cc], acc[cc][bb]);
        }
        __syncthreads();
    }
#pragma unroll
    for (int cc = 0; cc < 8; cc++) {
        int col = ct*128 + co + cc;
        float bv = __ldg(&bvec[col]);
        float4 o0 = make_float4(acc[cc][0]+bv, acc[cc][1]+bv, acc[cc][2]+bv, acc[cc][3]+bv);
        float4 o1 = make_float4(acc[cc][4]+bv, acc[cc][5]+bv, acc[cc][6]+bv, acc[cc][7]+bv);
        float* dst = (col < 2*Hdim)
            ? g_preZ + (size_t)i*(2*Hdim*Bdim) + (size_t)col*Bdim + bo
            : g_preC + (size_t)i*(Hdim*Bdim) + (size_t)(col - 2*Hdim)*Bdim + bo;
        *(float4*)dst = o0;
        *(float4*)(dst + 4) = o1;
    }
}

// ---------------- precompute GEMM: gamma_h = exp(-relu(delta@Wgh + b)) -------
// grid (4, 256). Same tile structure, K=512.
__global__ void __launch_bounds__(256, 2) k_gamma(const float* __restrict__ Wgh,
                                                  const float* __restrict__ bgh) {
    extern __shared__ float sm[];
    float* sA = sm;
    float* sW = sm + 8192;
    int ct = blockIdx.x, i = blockIdx.y, tid = threadIdx.x;
    const float* Ad = g_deltaS + (size_t)i*(Hdim*Bdim);
    int bo = (tid & 15) * 8;
    int co = (tid >> 4) * 8;
    float acc[8][8] = {};

    auto load = [&](int ck, int buf) {
#pragma unroll
        for (int v = 0; v < 4; v++) {
            int idx = tid + v*256;
            int kk  = idx >> 5;
            int q   = (idx & 31) * 4;
            int k   = ck*32 + kk;
            cp16(sA + buf*4096 + idx*4, Ad + (size_t)k*Bdim + q);
            cp16(sW + buf*4096 + idx*4, Wgh + (size_t)k*Hdim + ct*128 + q);
        }
    };

    load(0, 0); CP_COMMIT;
    for (int ck = 0; ck < 16; ck++) {
        if (ck < 15) { load(ck+1, (ck+1)&1); CP_COMMIT; CP_WAIT1; } else { CP_WAIT0; }
        __syncthreads();
        const float* A = sA + (ck&1)*4096;
        const float* W = sW + (ck&1)*4096;
#pragma unroll 4
        for (int k = 0; k < 32; k++) {
            float4 a0 = *(const float4*)(A + k*128 + bo);
            float4 a1 = *(const float4*)(A + k*128 + bo + 4);
            float4 w0 = *(const float4*)(W + k*128 + co);
            float4 w1 = *(const float4*)(W + k*128 + co + 4);
            float av[8] = {a0.x,a0.y,a0.z,a0.w,a1.x,a1.y,a1.z,a1.w};
            float wv[8] = {w0.x,w0.y,w0.z,w0.w,w1.x,w1.y,w1.z,w1.w};
#pragma unroll
            for (int cc = 0; cc < 8; cc++)
#pragma unroll
                for (int bb = 0; bb < 8; bb++)
                    acc[cc][bb] = fmaf(av[bb], wv[cc], acc[cc][bb]);
        }
        __syncthreads();
    }
#pragma unroll
    for (int cc = 0; cc < 8; cc++) {
        int col = ct*128 + co + cc;
        float bv = __ldg(&bgh[col]);
        float* dst = g_gamma + (size_t)i*(Hdim*Bdim) + (size_t)col*Bdim + bo;
#pragma unroll
        for (int bb = 0; bb < 8; bb++)
            dst[bb] = __expf(-fmaxf(0.f, acc[cc][bb] + bv));
    }
}

// ---------------- persistent recurrence: 2 barriers per step -----------------
// CTA c owns zr cols {c+128j, j=0..7} and h cols {4c..4c+3}.
// SMEM: sA 2x[128][128] (128KB) | sWhzr [512][8] 16KB | sWh3 [512][4] 8KB | sRed 32KB
#define MAIN_SMEM_FLOATS (32768 + 4096 + 2048 + 8192)
__global__ void __launch_bounds__(512, 1) k_main(const float* __restrict__ Wh) {
    extern __shared__ float sm[];
    float* sA    = sm;                // 2 x 16384
    float* sWhzr = sm + 32768;        // 4096
    float* sWh3  = sm + 36864;        // 2048
    float* sRed  = sm + 38912;        // 8192

    const int c   = blockIdx.x;
    const int tid = threadIdx.x;

    for (int idx = tid; idx < 4096; idx += 512) {
        int k = idx >> 3, j = idx & 7;
        sWhzr[idx] = Wh[(size_t)k*1536 + c + 128*j];
    }
    for (int idx = tid; idx < 2048; idx += 512) {
        int k = idx >> 2, j = idx & 3;
        sWh3[idx] = Wh[(size_t)k*1536 + 1024 + 4*c + j];
    }
    __syncthreads();

    const int rq = tid & 31;
    const int b0 = rq * 4;
    const int qt  = (tid >> 5) & 1;   // phase-1 col half
    const int kg  = tid >> 6;         // phase-1 K-group (8)
    const int kg2 = tid >> 5;         // phase-2 K-group (16)
    const int rcol = tid >> 7;        // 0..3 (phase-2 output col / phase-1 pairing)
    const int rb   = tid & 127;       // output batch index for reductions
    unsigned epoch = 0;

    auto stage = [&](const float* src, int ck, int buf) {
#pragma unroll
        for (int v = 0; v < 8; v++) {
            int idx = tid + v*512;       // float4 idx 0..4095
            cp16(sA + buf*16384 + idx*4, src + (size_t)ck*16384 + idx*4);
        }
    };

    for (int i = 0; i < Ldim; i++) {
        // ========== Phase 1: zr = sigmoid(preZ + h_scaled @ Wh_zr) ==========
        {
            float acc[4][4] = {};        // [j][r]
            stage(g_hsT, 0, 0); CP_COMMIT;
            for (int ck = 0; ck < 4; ck++) {
                if (ck < 3) { stage(g_hsT, ck+1, (ck+1)&1); CP_COMMIT; CP_WAIT1; }
                else        { CP_WAIT0; }
                __syncthreads();
                const float* A = sA + (ck&1)*16384;
#pragma unroll
                for (int k = 0; k < 16; k++) {
                    int row = kg*16 + k;
                    float4 a = *(const float4*)(A + row*128 + b0);
                    int kglob = ck*128 + row;
                    float4 w = *(const float4*)(sWhzr + kglob*8 + qt*4);
                    acc[0][0] = fmaf(a.x, w.x, acc[0][0]);
                    acc[0][1] = fmaf(a.y, w.x, acc[0][1]);
                    acc[0][2] = fmaf(a.z, w.x, acc[0][2]);
                    acc[0][3] = fmaf(a.w, w.x, acc[0][3]);
                    acc[1][0] = fmaf(a.x, w.y, acc[1][0]);
                    acc[1][1] = fmaf(a.y, w.y, acc[1][1]);
                    acc[1][2] = fmaf(a.z, w.y, acc[1][2]);
                    acc[1][3] = fmaf(a.w, w.y, acc[1][3]);
                    acc[2][0] = fmaf(a.x, w.z, acc[2][0]);
                    acc[2][1] = fmaf(a.y, w.z, acc[2][1]);
                    acc[2][2] = fmaf(a.z, w.z, acc[2][2]);
                    acc[2][3] = fmaf(a.w, w.z, acc[2][3]);
                    acc[3][0] = fmaf(a.x, w.w, acc[3][0]);
                    acc[3][1] = fmaf(a.y, w.w, acc[3][1]);
                    acc[3][2] = fmaf(a.z, w.w, acc[3][2]);
                    acc[3][3] = fmaf(a.w, w.w, acc[3][3]);
                }
                __syncthreads();
            }
            // reduce 8 K-groups
#pragma unroll
            for (int j = 0; j < 4; j++)
                *(float4*)(sRed + kg*1024 + (qt*4 + j)*128 + b0) =
                    make_float4(acc[j][0], acc[j][1], acc[j][2], acc[j][3]);
            __syncthreads();
#pragma unroll
            for (int o = 0; o < 2; o++) {
                int idx  = tid + o*512;     // 0..1023
                int col8 = idx >> 7;
                int b    = idx & 127;
                float s = 0.f;
#pragma unroll
                for (int kk = 0; kk < 8; kk++)
                    s += sRed[kk*1024 + col8*128 + b];
                int zrcol = c + 128*col8;
                s += __ldg(&g_preZ[(size_t)i*(2*Hdim*Bdim) + (size_t)zrcol*Bdim + b]);
                float sg = 1.f / (1.f + __expf(-s));
                if (col8 < 4) {
                    g_zT[zrcol*Bdim + b] = sg;
                } else {
                    int hc = zrcol - Hdim;
                    g_rhT[hc*Bdim + b] = sg * __ldcg(&g_hsT[hc*Bdim + b]);
                }
            }
        }
        grid_barrier(epoch);

        // ========== Phase 2: h_tilde = tanh(preC + rh @ Wh3); update h ======
        {
            float acc[4][4] = {};        // [col][r]
            stage(g_rhT, 0, 0); CP_COMMIT;
            for (int ck = 0; ck < 4; ck++) {
                if (ck < 3) { stage(g_rhT, ck+1, (ck+1)&1); CP_COMMIT; CP_WAIT1; }
                else        { CP_WAIT0; }
                __syncthreads();
                const float* A = sA + (ck&1)*16384;
#pragma unroll
                for (int k = 0; k < 8; k++) {
                    int row = kg2*8 + k;
                    float4 a = *(const float4*)(A + row*128 + b0);
                    int kglob = ck*128 + row;
                    float4 w = *(const float4*)(sWh3 + kglob*4);
                    acc[0][0] = fmaf(a.x, w.x, acc[0][0]);
                    acc[0][1] = fmaf(a.y, w.x, acc[0][1]);
                    acc[0][2] = fmaf(a.z, w.x, acc[0][2]);
                    acc[0][3] = fmaf(a.w, w.x, acc[0][3]);
                    acc[1][0] = fmaf(a.x, w.y, acc[1][0]);
                    acc[1][1] = fmaf(a.y, w.y, acc[1][1]);
                    acc[1][2] = fmaf(a.z, w.y, acc[1][2]);
                    acc[1][3] = fmaf(a.w, w.y, acc[1][3]);
                    acc[2][0] = fmaf(a.x, w.z, acc[2][0]);
                    acc[2][1] = fmaf(a.y, w.z, acc[2][1]);
                    acc[2][2] = fmaf(a.z, w.z, acc[2][2]);
                    acc[2][3] = fmaf(a.w, w.z, acc[2][3]);
                    acc[3][0] = fmaf(a.x, w.w, acc[3][0]);
                    acc[3][1] = fmaf(a.y, w.w, acc[3][1]);
                    acc[3][2] = fmaf(a.z, w.w, acc[3][2]);
                    acc[3][3] = fmaf(a.w, w.w, acc[3][3]);
                }
                __syncthreads();
            }
            // reduce 16 K-groups
#pragma unroll
            for (int j = 0; j < 4; j++)
                *(float4*)(sRed + kg2*512 + j*128 + b0) =
                    make_float4(acc[j][0], acc[j][1], acc[j][2], acc[j][3]);
            __syncthreads();
            {
                int col4 = rcol;
                int b    = rb;
                float s = 0.f;
#pragma unroll
                for (int kk = 0; kk < 16; kk++)
                    s += sRed[kk*512 + col4*128 + b];
                int col = 4*c + col4;
                int idx = col*Bdim + b;
                float ht = tanhf(s + __ldg(&g_preC[(size_t)i*(Hdim*Bdim) + idx]));
                float z  = __ldcg(&g_zT[idx]);
                float hs = __ldcg(&g_hsT[idx]);
                float hn = (1.f - z)*hs + z*ht;
                g_hseq[(size_t)i*(Hdim*Bdim) + idx] = hn;
                if (i + 1 < Ldim)
                    g_hsT[idx] = hn * __ldg(&g_gamma[(size_t)(i+1)*(Hdim*Bdim) + idx]);
            }
        }
        grid_barrier(epoch);
    }
}

// ---------------- final output GEMM: out = h_seq @ W_out + b_out -------------
__global__ void __launch_bounds__(256) k_out(const float* __restrict__ Wout,
                                             const float* __restrict__ bout,
                                             float* __restrict__ out) {
    extern __shared__ float sW[];      // [512][64]
    int i  = blockIdx.x;
    int oy = blockIdx.y;
    int tid = threadIdx.x;
    for (int idx = tid; idx < 512*64; idx += 256) {
        int k = idx >> 6, o = idx & 63;
        sW[idx] = Wout[(size_t)k*OUTdim + oy*64 + o];
    }
    __syncthreads();
    int rq = tid & 31;  int b0 = rq*4;
    int ot = tid >> 5;
    float acc[4][8] = {};
    const float* A = g_hseq + (size_t)i*(Hdim*Bdim);
#pragma unroll 2
    for (int k = 0; k < Hdim; k++) {
        float4 a4 = *reinterpret_cast<const float4*>(A + (size_t)k*Bdim + b0);
#pragma unroll
        for (int o = 0; o < 8; o++) {
            float w = sW[k*64 + ot*8 + o];
            acc[0][o] = fmaf(a4.x, w, acc[0][o]);
            acc[1][o] = fmaf(a4.y, w, acc[1][o]);
            acc[2][o] = fmaf(a4.z, w, acc[2][o]);
            acc[3][o] = fmaf(a4.w, w, acc[3][o]);
        }
    }
    int o0 = oy*64 + ot*8;
#pragma unroll
    for (int r2 = 0; r2 < 4; r2++) {
        int b = b0 + r2;
#pragma unroll
        for (int o = 0; o < 8; o++)
            out[((size_t)b*Ldim + i)*OUTdim + o0 + o] = acc[r2][o] + __ldg(&bout[o0 + o]);
    }
}

// ---------------- launch ------------------------------------------------------
extern "C" void kernel_launch(void* const* d_in, const int* in_sizes, int n_in,
                              void* d_out, int out_size) {
    const float* C    = (const float*)d_in[0];
    const float* t    = (const float*)d_in[1];
    const int*   mask = (const int*)  d_in[2];
    const float* Wx   = (const float*)d_in[3];
    const float* Wh   = (const float*)d_in[4];
    const float* Wm   = (const float*)d_in[5];
    const float* bvec = (const float*)d_in[6];
    const float* wgx  = (const float*)d_in[7];
    const float* bgx  = (const float*)d_in[8];
    const float* Wgh  = (const float*)d_in[9];
    const float* bgh  = (const float*)d_in[10];
    const float* Wout = (const float*)d_in[11];
    const float* bout = (const float*)d_in[12];
    float* out = (float*)d_out;

    cudaFuncSetAttribute(k_main, cudaFuncAttributeMaxDynamicSharedMemorySize,
                         MAIN_SMEM_FLOATS * 4);
    cudaFuncSetAttribute(k_pre, cudaFuncAttributeMaxDynamicSharedMemorySize, 65536);
    cudaFuncSetAttribute(k_gamma, cudaFuncAttributeMaxDynamicSharedMemorySize, 65536);
    cudaFuncSetAttribute(k_out, cudaFuncAttributeMaxDynamicSharedMemorySize, 512*64*4);

    dim3 tb(32, 8);
    dim3 tg((Ldim*Hdim)/32, Bdim/32);
    k_transpose_mask<<<tg, tb>>>(mask);
    k_setup<<<Bdim, Hdim>>>(C, t, mask);
    k_scan<<<NCTA, 512>>>(C, wgx, bgx);
    k_pre<<<dim3(12, Ldim), 256, 65536>>>(Wx, Wm, bvec);
    k_gamma<<<dim3(4, Ldim), 256, 65536>>>(Wgh, bgh);
    k_main<<<NCTA, 512, MAIN_SMEM_FLOATS * 4>>>(Wh);
    k_out<<<dim3(Ldim, 4), 256, 512*64*4>>>(Wout, bout, out);
}

// round 4
// speedup vs baseline: 7.2779x; 1.2691x over previous
#include <cuda_runtime.h>
#include <math.h>
#include <stdint.h>

#define Bdim 128
#define Hdim 512
#define Ldim 256
#define OUTdim 256
#define NCTA 128

// ---------------- persistent state & precomputed sequences ------------------
__device__ __align__(128) float g_xmeanBH[Bdim*Hdim];               // [b][h]
__device__ __align__(128) float g_dtT   [Ldim*Bdim];
__device__ __align__(128) float g_hsT   [Hdim*Bdim];                // h_scaled (recurrent) [h][b]
__device__ __align__(128) float g_zT    [Hdim*Bdim];
__device__ __align__(128) float g_rhT   [Hdim*Bdim];
__device__ __align__(128) float g_maskf [(size_t)Bdim*Ldim*Hdim];   // mask as float [b][i][h]
__device__ __align__(128) float g_xhatS [(size_t)Ldim*Bdim*Hdim];   // x_hat [i][b][h]
__device__ __align__(128) float g_deltaS[(size_t)Ldim*Bdim*Hdim];   // delta [i][b][h]
__device__ __align__(128) float g_preZ  [(size_t)Ldim*2*Hdim*Bdim]; // zr pre-act (+bias) [i][col][b]
__device__ __align__(128) float g_preC  [(size_t)Ldim*Hdim*Bdim];   // cand pre-act (+bias) [i][col][b]
__device__ __align__(128) float g_gamma [(size_t)Ldim*Hdim*Bdim];   // gamma_h [i][col][b]
__device__ __align__(128) float g_hseq  [(size_t)Ldim*Hdim*Bdim];   // recurrence outputs [i][h][b]
__device__ unsigned g_bar_count;
__device__ unsigned g_bar_epoch;

// ---------------- cp.async helpers ------------------------------------------
__device__ __forceinline__ void cp16(void* s, const void* g) {
    unsigned sa = (unsigned)__cvta_generic_to_shared(s);
    asm volatile("cp.async.cg.shared.global [%0], [%1], 16;\n" :: "r"(sa), "l"(g));
}
#define CP_COMMIT asm volatile("cp.async.commit_group;\n" ::: "memory")
#define CP_WAIT1  asm volatile("cp.async.wait_group 1;\n" ::: "memory")
#define CP_WAIT0  asm volatile("cp.async.wait_group 0;\n" ::: "memory")

// ---------------- tf32 mma helpers ------------------------------------------
__device__ __forceinline__ unsigned f2tf32(float x) {
    unsigned r;
    asm("cvt.rna.tf32.f32 %0, %1;" : "=r"(r) : "f"(x));
    return r;
}
__device__ __forceinline__ void mma_tf32(float c[4],
    unsigned a0, unsigned a1, unsigned a2, unsigned a3,
    unsigned b0, unsigned b1) {
    asm volatile(
        "mma.sync.aligned.m16n8k8.row.col.f32.tf32.tf32.f32 "
        "{%0,%1,%2,%3}, {%4,%5,%6,%7}, {%8,%9}, {%0,%1,%2,%3};"
        : "+f"(c[0]), "+f"(c[1]), "+f"(c[2]), "+f"(c[3])
        : "r"(a0), "r"(a1), "r"(a2), "r"(a3), "r"(b0), "r"(b1));
}

// ---------------- grid barrier (128 co-resident CTAs) -----------------------
__device__ __forceinline__ void grid_barrier(unsigned &epoch) {
    __threadfence();
    __syncthreads();
    if (threadIdx.x == 0) {
        unsigned old = atomicAdd(&g_bar_count, 1);
        if (old == gridDim.x - 1) {
            g_bar_count = 0;
            __threadfence();
            atomicAdd(&g_bar_epoch, 1);
        } else {
            while (*(volatile unsigned*)&g_bar_epoch == epoch) { __nanosleep(32); }
        }
    }
    epoch++;
    __syncthreads();
}

// ---------------- mask int -> float (same [b][i][h] layout) -----------------
__global__ void k_maskf(const int* __restrict__ mask) {
    size_t idx = (size_t)blockIdx.x * 1024 + threadIdx.x;
    g_maskf[idx] = (float)mask[idx];
}

// ---------------- setup: x_mean, dt, barrier reset ---------------------------
__global__ void k_setup(const float* __restrict__ C, const float* __restrict__ t,
                        const int* __restrict__ mask) {
    int b = blockIdx.x;
    int h = threadIdx.x;                 // 512
    float s1 = 0.f, s0 = 0.f;
    for (int i = 0; i < Ldim; i++) {
        float m = (float)mask[((size_t)b*Ldim + i)*Hdim + h];
        s1 += m * C[i*Hdim + h];
        s0 += m;
    }
    g_xmeanBH[b*Hdim + h] = s1 / fmaxf(s0, 1.f);
    if (h < Ldim) {
        int i = h;
        g_dtT[i*Bdim + b] = (i == 0) ? 0.f : (t[b*Ldim + i] - t[b*Ldim + i - 1]);
    }
    if (b == 0 && h == 0) { g_bar_count = 0; g_bar_epoch = 0; }
}

// ---------------- elementwise scan: delta[i], x_hat[i] ([i][b][h]) -----------
__global__ void __launch_bounds__(512) k_scan(const float* __restrict__ C,
                                              const float* __restrict__ w_gx,
                                              const float* __restrict__ b_gx) {
    int gid = blockIdx.x * 512 + threadIdx.x;   // 65536
    int b = gid >> 9, h = gid & 511;
    float xm = g_xmeanBH[b*Hdim + h];
    float x_last = xm, delta = 0.f, m_prev = 1.f;
    float wg = __ldg(&w_gx[h]), bg = __ldg(&b_gx[h]);
    for (int i = 0; i < Ldim; i++) {
        float dti = g_dtT[i*Bdim + b];
        delta = dti + (1.f - m_prev) * delta;
        float m  = g_maskf[((size_t)b*Ldim + i)*Hdim + h];
        float xi = __ldg(&C[i*Hdim + h]);
        float gx = __expf(-fmaxf(0.f, wg*delta + bg));
        size_t idx = ((size_t)i*Bdim + b)*Hdim + h;
        g_xhatS[idx]  = m*xi + (1.f - m)*(gx*x_last + (1.f - gx)*xm);
        g_deltaS[idx] = delta;
        x_last = m*xi + (1.f - m)*x_last;
        m_prev = m;
    }
    g_hsT[h*Bdim + b] = 0.f;   // h_scaled init (h0 = 0)
}

// ---------------- tf32 tensor GEMM: pre = [xhat;m] @ [Wx;Wm] + b -------------
// grid (12, 256). block 256 thr (8 warps, 2x4). tile M=128(batch) N=128(cols) K=1024.
#define PAD_A 36
#define PAD_B 136
#define PRE_SMEM ((2*128*PAD_A + 2*32*PAD_B)*4)
__global__ void __launch_bounds__(256, 2) k_pre(const float* __restrict__ Wx,
                                                const float* __restrict__ Wm,
                                                const float* __restrict__ bvec) {
    extern __shared__ float sm[];
    float* sA = sm;                     // 2 x 128 x 36
    float* sB = sm + 2*128*PAD_A;       // 2 x 32 x 136
    int ct = blockIdx.x, i = blockIdx.y, tid = threadIdx.x;
    int lane = tid & 31, warp = tid >> 5;
    int wm = warp & 1, wn = warp >> 1;

    auto loadA = [&](int ck, int buf) {
        int k0 = ck*32;
#pragma unroll
        for (int v = 0; v < 4; v++) {
            int idx = tid + v*256;
            int b = idx >> 3;
            int kq = (idx & 7) * 4;
            const float* src = (k0 < Hdim)
                ? g_xhatS + ((size_t)i*Bdim + b)*Hdim + k0 + kq
                : g_maskf + ((size_t)b*Ldim + i)*Hdim + (k0 - Hdim) + kq;
            cp16(sA + buf*128*PAD_A + b*PAD_A + kq, src);
        }
    };
    auto loadB = [&](int ck, int buf) {
        int k0 = ck*32;
#pragma unroll
        for (int v = 0; v < 4; v++) {
            int idx = tid + v*256;
            int k = idx >> 5;
            int q = (idx & 31) * 4;
            const float* src = (k0 < Hdim
                ? Wx + (size_t)(k0 + k)*1536
                : Wm + (size_t)(k0 - Hdim + k)*1536) + ct*128 + q;
            cp16(sB + buf*32*PAD_B + k*PAD_B + q, src);
        }
    };

    float c[4][4][4] = {};
    loadA(0, 0); loadB(0, 0); CP_COMMIT;
    for (int ck = 0; ck < 32; ck++) {
        if (ck < 31) { loadA(ck+1, (ck+1)&1); loadB(ck+1, (ck+1)&1); CP_COMMIT; CP_WAIT1; }
        else         { CP_WAIT0; }
        __syncthreads();
        const float* A = sA + (ck&1)*128*PAD_A;
        const float* B = sB + (ck&1)*32*PAD_B;
#pragma unroll
        for (int ks = 0; ks < 4; ks++) {
            unsigned af[4][4], bf[4][2];
#pragma unroll
            for (int mi = 0; mi < 4; mi++) {
                int r  = wm*64 + mi*16 + (lane >> 2);
                int cc = ks*8 + (lane & 3);
                af[mi][0] = f2tf32(A[r*PAD_A + cc]);
                af[mi][1] = f2tf32(A[(r+8)*PAD_A + cc]);
                af[mi][2] = f2tf32(A[r*PAD_A + cc + 4]);
                af[mi][3] = f2tf32(A[(r+8)*PAD_A + cc + 4]);
            }
#pragma unroll
            for (int ni = 0; ni < 4; ni++) {
                int n  = wn*32 + ni*8 + (lane >> 2);
                int kk = ks*8 + (lane & 3);
                bf[ni][0] = f2tf32(B[kk*PAD_B + n]);
                bf[ni][1] = f2tf32(B[(kk+4)*PAD_B + n]);
            }
#pragma unroll
            for (int mi = 0; mi < 4; mi++)
#pragma unroll
                for (int ni = 0; ni < 4; ni++)
                    mma_tf32(c[mi][ni], af[mi][0], af[mi][1], af[mi][2], af[mi][3],
                             bf[ni][0], bf[ni][1]);
        }
        __syncthreads();
    }
    // epilogue: +bias, store transposed to [i][col][b]
#pragma unroll
    for (int mi = 0; mi < 4; mi++) {
        int r0 = wm*64 + mi*16 + (lane >> 2);
#pragma unroll
        for (int ni = 0; ni < 4; ni++) {
            int col0 = ct*128 + wn*32 + ni*8 + (lane & 3)*2;
            float bv0 = __ldg(&bvec[col0]);
            float bv1 = __ldg(&bvec[col0 + 1]);
            float* d0;
            float* d1;
            if (ct < 8) {
                d0 = g_preZ + (size_t)i*(2*Hdim*Bdim) + (size_t)col0*Bdim;
                d1 = d0 + Bdim;
            } else {
                d0 = g_preC + (size_t)i*(Hdim*Bdim) + (size_t)(col0 - 2*Hdim)*Bdim;
                d1 = d0 + Bdim;
            }
            d0[r0]     = c[mi][ni][0] + bv0;
            d1[r0]     = c[mi][ni][1] + bv1;
            d0[r0 + 8] = c[mi][ni][2] + bv0;
            d1[r0 + 8] = c[mi][ni][3] + bv1;
        }
    }
}

// ---------------- tf32 tensor GEMM: gamma = exp(-relu(delta@Wgh + b)) --------
// grid (4, 256). tile 128x128, K=512.
__global__ void __launch_bounds__(256, 2) k_gamma(const float* __restrict__ Wgh,
                                                  const float* __restrict__ bgh) {
    extern __shared__ float sm[];
    float* sA = sm;
    float* sB = sm + 2*128*PAD_A;
    int ct = blockIdx.x, i = blockIdx.y, tid = threadIdx.x;
    int lane = tid & 31, warp = tid >> 5;
    int wm = warp & 1, wn = warp >> 1;

    auto loadA = [&](int ck, int buf) {
        int k0 = ck*32;
#pragma unroll
        for (int v = 0; v < 4; v++) {
            int idx = tid + v*256;
            int b = idx >> 3;
            int kq = (idx & 7) * 4;
            cp16(sA + buf*128*PAD_A + b*PAD_A + kq,
                 g_deltaS + ((size_t)i*Bdim + b)*Hdim + k0 + kq);
        }
    };
    auto loadB = [&](int ck, int buf) {
        int k0 = ck*32;
#pragma unroll
        for (int v = 0; v < 4; v++) {
            int idx = tid + v*256;
            int k = idx >> 5;
            int q = (idx & 31) * 4;
            cp16(sB + buf*32*PAD_B + k*PAD_B + q,
                 Wgh + (size_t)(k0 + k)*Hdim + ct*128 + q);
        }
    };

    float c[4][4][4] = {};
    loadA(0, 0); loadB(0, 0); CP_COMMIT;
    for (int ck = 0; ck < 16; ck++) {
        if (ck < 15) { loadA(ck+1, (ck+1)&1); loadB(ck+1, (ck+1)&1); CP_COMMIT; CP_WAIT1; }
        else         { CP_WAIT0; }
        __syncthreads();
        const float* A = sA + (ck&1)*128*PAD_A;
        const float* B = sB + (ck&1)*32*PAD_B;
#pragma unroll
        for (int ks = 0; ks < 4; ks++) {
            unsigned af[4][4], bf[4][2];
#pragma unroll
            for (int mi = 0; mi < 4; mi++) {
                int r  = wm*64 + mi*16 + (lane >> 2);
                int cc = ks*8 + (lane & 3);
                af[mi][0] = f2tf32(A[r*PAD_A + cc]);
                af[mi][1] = f2tf32(A[(r+8)*PAD_A + cc]);
                af[mi][2] = f2tf32(A[r*PAD_A + cc + 4]);
                af[mi][3] = f2tf32(A[(r+8)*PAD_A + cc + 4]);
            }
#pragma unroll
            for (int ni = 0; ni < 4; ni++) {
                int n  = wn*32 + ni*8 + (lane >> 2);
                int kk = ks*8 + (lane & 3);
                bf[ni][0] = f2tf32(B[kk*PAD_B + n]);
                bf[ni][1] = f2tf32(B[(kk+4)*PAD_B + n]);
            }
#pragma unroll
            for (int mi = 0; mi < 4; mi++)
#pragma unroll
                for (int ni = 0; ni < 4; ni++)
                    mma_tf32(c[mi][ni], af[mi][0], af[mi][1], af[mi][2], af[mi][3],
                             bf[ni][0], bf[ni][1]);
        }
        __syncthreads();
    }
#pragma unroll
    for (int mi = 0; mi < 4; mi++) {
        int r0 = wm*64 + mi*16 + (lane >> 2);
#pragma unroll
        for (int ni = 0; ni < 4; ni++) {
            int col0 = ct*128 + wn*32 + ni*8 + (lane & 3)*2;
            float bv0 = __ldg(&bgh[col0]);
            float bv1 = __ldg(&bgh[col0 + 1]);
            float* d0 = g_gamma + (size_t)i*(Hdim*Bdim) + (size_t)col0*Bdim;
            float* d1 = d0 + Bdim;
            d0[r0]     = __expf(-fmaxf(0.f, c[mi][ni][0] + bv0));
            d1[r0]     = __expf(-fmaxf(0.f, c[mi][ni][1] + bv1));
            d0[r0 + 8] = __expf(-fmaxf(0.f, c[mi][ni][2] + bv0));
            d1[r0 + 8] = __expf(-fmaxf(0.f, c[mi][ni][3] + bv1));
        }
    }
}

// ---------------- persistent recurrence: 2 barriers per step -----------------
#define MAIN_SMEM_FLOATS (32768 + 4096 + 2048 + 8192)
__global__ void __launch_bounds__(512, 1) k_main(const float* __restrict__ Wh) {
    extern __shared__ float sm[];
    float* sA    = sm;                // 2 x 16384
    float* sWhzr = sm + 32768;        // 4096
    float* sWh3  = sm + 36864;        // 2048
    float* sRed  = sm + 38912;        // 8192

    const int c   = blockIdx.x;
    const int tid = threadIdx.x;

    for (int idx = tid; idx < 4096; idx += 512) {
        int k = idx >> 3, j = idx & 7;
        sWhzr[idx] = Wh[(size_t)k*1536 + c + 128*j];
    }
    for (int idx = tid; idx < 2048; idx += 512) {
        int k = idx >> 2, j = idx & 3;
        sWh3[idx] = Wh[(size_t)k*1536 + 1024 + 4*c + j];
    }
    __syncthreads();

    const int rq = tid & 31;
    const int b0 = rq * 4;
    const int qt  = (tid >> 5) & 1;
    const int kg  = tid >> 6;
    const int kg2 = tid >> 5;
    const int rcol = tid >> 7;
    const int rb   = tid & 127;
    unsigned epoch = 0;

    auto stage = [&](const float* src, int ck, int buf) {
#pragma unroll
        for (int v = 0; v < 8; v++) {
            int idx = tid + v*512;
            cp16(sA + buf*16384 + idx*4, src + (size_t)ck*16384 + idx*4);
        }
    };

    for (int i = 0; i < Ldim; i++) {
        // ========== Phase 1: zr = sigmoid(preZ + h_scaled @ Wh_zr) ==========
        {
            float acc[4][4] = {};
            stage(g_hsT, 0, 0); CP_COMMIT;
            for (int ck = 0; ck < 4; ck++) {
                if (ck < 3) { stage(g_hsT, ck+1, (ck+1)&1); CP_COMMIT; CP_WAIT1; }
                else        { CP_WAIT0; }
                __syncthreads();
                const float* A = sA + (ck&1)*16384;
#pragma unroll
                for (int k = 0; k < 16; k++) {
                    int row = kg*16 + k;
                    float4 a = *(const float4*)(A + row*128 + b0);
                    int kglob = ck*128 + row;
                    float4 w = *(const float4*)(sWhzr + kglob*8 + qt*4);
                    acc[0][0] = fmaf(a.x, w.x, acc[0][0]);
                    acc[0][1] = fmaf(a.y, w.x, acc[0][1]);
                    acc[0][2] = fmaf(a.z, w.x, acc[0][2]);
                    acc[0][3] = fmaf(a.w, w.x, acc[0][3]);
                    acc[1][0] = fmaf(a.x, w.y, acc[1][0]);
                    acc[1][1] = fmaf(a.y, w.y, acc[1][1]);
                    acc[1][2] = fmaf(a.z, w.y, acc[1][2]);
                    acc[1][3] = fmaf(a.w, w.y, acc[1][3]);
                    acc[2][0] = fmaf(a.x, w.z, acc[2][0]);
                    acc[2][1] = fmaf(a.y, w.z, acc[2][1]);
                    acc[2][2] = fmaf(a.z, w.z, acc[2][2]);
                    acc[2][3] = fmaf(a.w, w.z, acc[2][3]);
                    acc[3][0] = fmaf(a.x, w.w, acc[3][0]);
                    acc[3][1] = fmaf(a.y, w.w, acc[3][1]);
                    acc[3][2] = fmaf(a.z, w.w, acc[3][2]);
                    acc[3][3] = fmaf(a.w, w.w, acc[3][3]);
                }
                __syncthreads();
            }
#pragma unroll
            for (int j = 0; j < 4; j++)
                *(float4*)(sRed + kg*1024 + (qt*4 + j)*128 + b0) =
                    make_float4(acc[j][0], acc[j][1], acc[j][2], acc[j][3]);
            __syncthreads();
#pragma unroll
            for (int o = 0; o < 2; o++) {
                int idx  = tid + o*512;
                int col8 = idx >> 7;
                int b    = idx & 127;
                float s = 0.f;
#pragma unroll
                for (int kk = 0; kk < 8; kk++)
                    s += sRed[kk*1024 + col8*128 + b];
                int zrcol = c + 128*col8;
                s += __ldg(&g_preZ[(size_t)i*(2*Hdim*Bdim) + (size_t)zrcol*Bdim + b]);
                float sg = 1.f / (1.f + __expf(-s));
                if (col8 < 4) {
                    g_zT[zrcol*Bdim + b] = sg;
                } else {
                    int hc = zrcol - Hdim;
                    g_rhT[hc*Bdim + b] = sg * __ldcg(&g_hsT[hc*Bdim + b]);
                }
            }
        }
        grid_barrier(epoch);

        // ========== Phase 2: h_tilde = tanh(preC + rh @ Wh3); update h ======
        {
            float acc[4][4] = {};
            stage(g_rhT, 0, 0); CP_COMMIT;
            for (int ck = 0; ck < 4; ck++) {
                if (ck < 3) { stage(g_rhT, ck+1, (ck+1)&1); CP_COMMIT; CP_WAIT1; }
                else        { CP_WAIT0; }
                __syncthreads();
                const float* A = sA + (ck&1)*16384;
#pragma unroll
                for (int k = 0; k < 8; k++) {
                    int row = kg2*8 + k;
                    float4 a = *(const float4*)(A + row*128 + b0);
                    int kglob = ck*128 + row;
                    float4 w = *(const float4*)(sWh3 + kglob*4);
                    acc[0][0] = fmaf(a.x, w.x, acc[0][0]);
                    acc[0][1] = fmaf(a.y, w.x, acc[0][1]);
                    acc[0][2] = fmaf(a.z, w.x, acc[0][2]);
                    acc[0][3] = fmaf(a.w, w.x, acc[0][3]);
                    acc[1][0] = fmaf(a.x, w.y, acc[1][0]);
                    acc[1][1] = fmaf(a.y, w.y, acc[1][1]);
                    acc[1][2] = fmaf(a.z, w.y, acc[1][2]);
                    acc[1][3] = fmaf(a.w, w.y, acc[1][3]);
                    acc[2][0] = fmaf(a.x, w.z, acc[2][0]);
                    acc[2][1] = fmaf(a.y, w.z, acc[2][1]);
                    acc[2][2] = fmaf(a.z, w.z, acc[2][2]);
                    acc[2][3] = fmaf(a.w, w.z, acc[2][3]);
                    acc[3][0] = fmaf(a.x, w.w, acc[3][0]);
                    acc[3][1] = fmaf(a.y, w.w, acc[3][1]);
                    acc[3][2] = fmaf(a.z, w.w, acc[3][2]);
                    acc[3][3] = fmaf(a.w, w.w, acc[3][3]);
                }
                __syncthreads();
            }
#pragma unroll
            for (int j = 0; j < 4; j++)
                *(float4*)(sRed + kg2*512 + j*128 + b0) =
                    make_float4(acc[j][0], acc[j][1], acc[j][2], acc[j][3]);
            __syncthreads();
            {
                int col4 = rcol;
                int b    = rb;
                float s = 0.f;
#pragma unroll
                for (int kk = 0; kk < 16; kk++)
                    s += sRed[kk*512 + col4*128 + b];
                int col = 4*c + col4;
                int idx = col*Bdim + b;
                float ht = tanhf(s + __ldg(&g_preC[(size_t)i*(Hdim*Bdim) + idx]));
                float z  = __ldcg(&g_zT[idx]);
                float hs = __ldcg(&g_hsT[idx]);
                float hn = (1.f - z)*hs + z*ht;
                g_hseq[(size_t)i*(Hdim*Bdim) + idx] = hn;
                if (i + 1 < Ldim)
                    g_hsT[idx] = hn * __ldg(&g_gamma[(size_t)(i+1)*(Hdim*Bdim) + idx]);
            }
        }
        grid_barrier(epoch);
    }
}

// ---------------- final output GEMM: out = h_seq @ W_out + b_out -------------
__global__ void __launch_bounds__(256) k_out(const float* __restrict__ Wout,
                                             const float* __restrict__ bout,
                                             float* __restrict__ out) {
    extern __shared__ float sW[];      // [512][64]
    int i  = blockIdx.x;
    int oy = blockIdx.y;
    int tid = threadIdx.x;
    for (int idx = tid; idx < 512*64; idx += 256) {
        int k = idx >> 6, o = idx & 63;
        sW[idx] = Wout[(size_t)k*OUTdim + oy*64 + o];
    }
    __syncthreads();
    int rq = tid & 31;  int b0 = rq*4;
    int ot = tid >> 5;
    float acc[4][8] = {};
    const float* A = g_hseq + (size_t)i*(Hdim*Bdim);
#pragma unroll 2
    for (int k = 0; k < Hdim; k++) {
        float4 a4 = *reinterpret_cast<const float4*>(A + (size_t)k*Bdim + b0);
#pragma unroll
        for (int o = 0; o < 8; o++) {
            float w = sW[k*64 + ot*8 + o];
            acc[0][o] = fmaf(a4.x, w, acc[0][o]);
            acc[1][o] = fmaf(a4.y, w, acc[1][o]);
            acc[2][o] = fmaf(a4.z, w, acc[2][o]);
            acc[3][o] = fmaf(a4.w, w, acc[3][o]);
        }
    }
    int o0 = oy*64 + ot*8;
#pragma unroll
    for (int r2 = 0; r2 < 4; r2++) {
        int b = b0 + r2;
#pragma unroll
        for (int o = 0; o < 8; o++)
            out[((size_t)b*Ldim + i)*OUTdim + o0 + o] = acc[r2][o] + __ldg(&bout[o0 + o]);
    }
}

// ---------------- launch ------------------------------------------------------
extern "C" void kernel_launch(void* const* d_in, const int* in_sizes, int n_in,
                              void* d_out, int out_size) {
    const float* C    = (const float*)d_in[0];
    const float* t    = (const float*)d_in[1];
    const int*   mask = (const int*)  d_in[2];
    const float* Wx   = (const float*)d_in[3];
    const float* Wh   = (const float*)d_in[4];
    const float* Wm   = (const float*)d_in[5];
    const float* bvec = (const float*)d_in[6];
    const float* wgx  = (const float*)d_in[7];
    const float* bgx  = (const float*)d_in[8];
    const float* Wgh  = (const float*)d_in[9];
    const float* bgh  = (const float*)d_in[10];
    const float* Wout = (const float*)d_in[11];
    const float* bout = (const float*)d_in[12];
    float* out = (float*)d_out;

    cudaFuncSetAttribute(k_main, cudaFuncAttributeMaxDynamicSharedMemorySize,
                         MAIN_SMEM_FLOATS * 4);
    cudaFuncSetAttribute(k_pre, cudaFuncAttributeMaxDynamicSharedMemorySize, PRE_SMEM);
    cudaFuncSetAttribute(k_gamma, cudaFuncAttributeMaxDynamicSharedMemorySize, PRE_SMEM);
    cudaFuncSetAttribute(k_out, cudaFuncAttributeMaxDynamicSharedMemorySize, 512*64*4);

    k_maskf<<<(Bdim*Ldim*Hdim)/1024, 1024>>>(mask);
    k_setup<<<Bdim, Hdim>>>(C, t, mask);
    k_scan<<<128, 512>>>(C, wgx, bgx);
    k_pre<<<dim3(12, Ldim), 256, PRE_SMEM>>>(Wx, Wm, bvec);
    k_gamma<<<dim3(4, Ldim), 256, PRE_SMEM>>>(Wgh, bgh);
    k_main<<<NCTA, 512, MAIN_SMEM_FLOATS * 4>>>(Wh);
    k_out<<<dim3(Ldim, 4), 256, 512*64*4>>>(Wout, bout, out);
}

// round 5
// speedup vs baseline: 9.5644x; 1.3142x over previous
#include <cuda_runtime.h>
#include <math.h>
#include <stdint.h>

#define Bdim 128
#define Hdim 512
#define Ldim 256
#define OUTdim 256
#define NCTA 128

// ---------------- persistent state & precomputed sequences ------------------
__device__ __align__(128) float g_xmeanBH[Bdim*Hdim];               // [b][h]
__device__ __align__(128) float g_dtT   [Ldim*Bdim];
__device__ __align__(128) float g_hsT   [Hdim*Bdim];                // h_scaled (recurrent) [h][b]
__device__ __align__(128) float g_zT    [Hdim*Bdim];
__device__ __align__(128) float g_rhT   [Hdim*Bdim];
__device__ __align__(128) float g_maskf [(size_t)Bdim*Ldim*Hdim];   // mask as float [b][i][h]
__device__ __align__(128) float g_xhatS [(size_t)Ldim*Bdim*Hdim];   // x_hat [i][b][h]
__device__ __align__(128) float g_deltaS[(size_t)Ldim*Bdim*Hdim];   // delta [i][b][h]
__device__ __align__(128) float g_preZ  [(size_t)Ldim*2*Hdim*Bdim]; // zr pre-act (+bias) [i][col][b]
__device__ __align__(128) float g_preC  [(size_t)Ldim*Hdim*Bdim];   // cand pre-act (+bias) [i][col][b]
__device__ __align__(128) float g_gamma [(size_t)Ldim*Hdim*Bdim];   // gamma_h [i][col][b]
__device__ __align__(128) float g_hseq  [(size_t)Ldim*Hdim*Bdim];   // recurrence outputs [i][h][b]
__device__ unsigned g_bgbar_count[4];
__device__ unsigned g_bgbar_epoch[4];

// ---------------- cp.async helpers ------------------------------------------
__device__ __forceinline__ void cp16(void* s, const void* g) {
    unsigned sa = (unsigned)__cvta_generic_to_shared(s);
    asm volatile("cp.async.cg.shared.global [%0], [%1], 16;\n" :: "r"(sa), "l"(g));
}
#define CP_COMMIT asm volatile("cp.async.commit_group;\n" ::: "memory")
#define CP_WAIT1  asm volatile("cp.async.wait_group 1;\n" ::: "memory")
#define CP_WAIT0  asm volatile("cp.async.wait_group 0;\n" ::: "memory")

// ---------------- tf32 mma helpers ------------------------------------------
__device__ __forceinline__ unsigned f2tf32(float x) {
    unsigned r;
    asm("cvt.rna.tf32.f32 %0, %1;" : "=r"(r) : "f"(x));
    return r;
}
__device__ __forceinline__ void mma_tf32(float c[4],
    unsigned a0, unsigned a1, unsigned a2, unsigned a3,
    unsigned b0, unsigned b1) {
    asm volatile(
        "mma.sync.aligned.m16n8k8.row.col.f32.tf32.tf32.f32 "
        "{%0,%1,%2,%3}, {%4,%5,%6,%7}, {%8,%9}, {%0,%1,%2,%3};"
        : "+f"(c[0]), "+f"(c[1]), "+f"(c[2]), "+f"(c[3])
        : "r"(a0), "r"(a1), "r"(a2), "r"(a3), "r"(b0), "r"(b1));
}

// ---------------- per-batch-group barrier (32 CTAs each) ---------------------
__device__ __forceinline__ void bg_barrier(int bg, unsigned &epoch) {
    __threadfence();
    __syncthreads();
    if (threadIdx.x == 0) {
        unsigned old = atomicAdd(&g_bgbar_count[bg], 1);
        if (old == 31) {
            g_bgbar_count[bg] = 0;
            __threadfence();
            atomicAdd(&g_bgbar_epoch[bg], 1);
        } else {
            while (*(volatile unsigned*)&g_bgbar_epoch[bg] == epoch) { __nanosleep(32); }
        }
    }
    epoch++;
    __syncthreads();
}

// ---------------- mask int -> float (same [b][i][h] layout) -----------------
__global__ void k_maskf(const int* __restrict__ mask) {
    size_t idx = (size_t)blockIdx.x * 1024 + threadIdx.x;
    g_maskf[idx] = (float)mask[idx];
}

// ---------------- setup: x_mean, dt, barrier reset ---------------------------
__global__ void k_setup(const float* __restrict__ C, const float* __restrict__ t,
                        const int* __restrict__ mask) {
    int b = blockIdx.x;
    int h = threadIdx.x;                 // 512
    float s1 = 0.f, s0 = 0.f;
    for (int i = 0; i < Ldim; i++) {
        float m = (float)mask[((size_t)b*Ldim + i)*Hdim + h];
        s1 += m * C[i*Hdim + h];
        s0 += m;
    }
    g_xmeanBH[b*Hdim + h] = s1 / fmaxf(s0, 1.f);
    if (h < Ldim) {
        int i = h;
        g_dtT[i*Bdim + b] = (i == 0) ? 0.f : (t[b*Ldim + i] - t[b*Ldim + i - 1]);
    }
    if (b == 0 && h < 4) { g_bgbar_count[h] = 0; g_bgbar_epoch[h] = 0; }
}

// ---------------- elementwise scan: delta[i], x_hat[i] ([i][b][h]) -----------
__global__ void __launch_bounds__(512) k_scan(const float* __restrict__ C,
                                              const float* __restrict__ w_gx,
                                              const float* __restrict__ b_gx) {
    int gid = blockIdx.x * 512 + threadIdx.x;   // 65536
    int b = gid >> 9, h = gid & 511;
    float xm = g_xmeanBH[b*Hdim + h];
    float x_last = xm, delta = 0.f, m_prev = 1.f;
    float wg = __ldg(&w_gx[h]), bg = __ldg(&b_gx[h]);
    for (int i = 0; i < Ldim; i++) {
        float dti = g_dtT[i*Bdim + b];
        delta = dti + (1.f - m_prev) * delta;
        float m  = g_maskf[((size_t)b*Ldim + i)*Hdim + h];
        float xi = __ldg(&C[i*Hdim + h]);
        float gx = __expf(-fmaxf(0.f, wg*delta + bg));
        size_t idx = ((size_t)i*Bdim + b)*Hdim + h;
        g_xhatS[idx]  = m*xi + (1.f - m)*(gx*x_last + (1.f - gx)*xm);
        g_deltaS[idx] = delta;
        x_last = m*xi + (1.f - m)*x_last;
        m_prev = m;
    }
    g_hsT[h*Bdim + b] = 0.f;   // h_scaled init (h0 = 0)
}

// ---------------- tf32 tensor GEMM: pre = [xhat;m] @ [Wx;Wm] + b -------------
#define PAD_A 36
#define PAD_B 136
#define PRE_SMEM ((2*128*PAD_A + 2*32*PAD_B)*4)
__global__ void __launch_bounds__(256, 2) k_pre(const float* __restrict__ Wx,
                                                const float* __restrict__ Wm,
                                                const float* __restrict__ bvec) {
    extern __shared__ float sm[];
    float* sA = sm;                     // 2 x 128 x 36
    float* sB = sm + 2*128*PAD_A;       // 2 x 32 x 136
    int ct = blockIdx.x, i = blockIdx.y, tid = threadIdx.x;
    int lane = tid & 31, warp = tid >> 5;
    int wm = warp & 1, wn = warp >> 1;

    auto loadA = [&](int ck, int buf) {
        int k0 = ck*32;
#pragma unroll
        for (int v = 0; v < 4; v++) {
            int idx = tid + v*256;
            int b = idx >> 3;
            int kq = (idx & 7) * 4;
            const float* src = (k0 < Hdim)
                ? g_xhatS + ((size_t)i*Bdim + b)*Hdim + k0 + kq
                : g_maskf + ((size_t)b*Ldim + i)*Hdim + (k0 - Hdim) + kq;
            cp16(sA + buf*128*PAD_A + b*PAD_A + kq, src);
        }
    };
    auto loadB = [&](int ck, int buf) {
        int k0 = ck*32;
#pragma unroll
        for (int v = 0; v < 4; v++) {
            int idx = tid + v*256;
            int k = idx >> 5;
            int q = (idx & 31) * 4;
            const float* src = (k0 < Hdim
                ? Wx + (size_t)(k0 + k)*1536
                : Wm + (size_t)(k0 - Hdim + k)*1536) + ct*128 + q;
            cp16(sB + buf*32*PAD_B + k*PAD_B + q, src);
        }
    };

    float c[4][4][4] = {};
    loadA(0, 0); loadB(0, 0); CP_COMMIT;
    for (int ck = 0; ck < 32; ck++) {
        if (ck < 31) { loadA(ck+1, (ck+1)&1); loadB(ck+1, (ck+1)&1); CP_COMMIT; CP_WAIT1; }
        else         { CP_WAIT0; }
        __syncthreads();
        const float* A = sA + (ck&1)*128*PAD_A;
        const float* B = sB + (ck&1)*32*PAD_B;
#pragma unroll
        for (int ks = 0; ks < 4; ks++) {
            unsigned af[4][4], bf[4][2];
#pragma unroll
            for (int mi = 0; mi < 4; mi++) {
                int r  = wm*64 + mi*16 + (lane >> 2);
                int cc = ks*8 + (lane & 3);
                af[mi][0] = f2tf32(A[r*PAD_A + cc]);
                af[mi][1] = f2tf32(A[(r+8)*PAD_A + cc]);
                af[mi][2] = f2tf32(A[r*PAD_A + cc + 4]);
                af[mi][3] = f2tf32(A[(r+8)*PAD_A + cc + 4]);
            }
#pragma unroll
            for (int ni = 0; ni < 4; ni++) {
                int n  = wn*32 + ni*8 + (lane >> 2);
                int kk = ks*8 + (lane & 3);
                bf[ni][0] = f2tf32(B[kk*PAD_B + n]);
                bf[ni][1] = f2tf32(B[(kk+4)*PAD_B + n]);
            }
#pragma unroll
            for (int mi = 0; mi < 4; mi++)
#pragma unroll
                for (int ni = 0; ni < 4; ni++)
                    mma_tf32(c[mi][ni], af[mi][0], af[mi][1], af[mi][2], af[mi][3],
                             bf[ni][0], bf[ni][1]);
        }
        __syncthreads();
    }
#pragma unroll
    for (int mi = 0; mi < 4; mi++) {
        int r0 = wm*64 + mi*16 + (lane >> 2);
#pragma unroll
        for (int ni = 0; ni < 4; ni++) {
            int col0 = ct*128 + wn*32 + ni*8 + (lane & 3)*2;
            float bv0 = __ldg(&bvec[col0]);
            float bv1 = __ldg(&bvec[col0 + 1]);
            float* d0;
            float* d1;
            if (ct < 8) {
                d0 = g_preZ + (size_t)i*(2*Hdim*Bdim) + (size_t)col0*Bdim;
                d1 = d0 + Bdim;
            } else {
                d0 = g_preC + (size_t)i*(Hdim*Bdim) + (size_t)(col0 - 2*Hdim)*Bdim;
                d1 = d0 + Bdim;
            }
            d0[r0]     = c[mi][ni][0] + bv0;
            d1[r0]     = c[mi][ni][1] + bv1;
            d0[r0 + 8] = c[mi][ni][2] + bv0;
            d1[r0 + 8] = c[mi][ni][3] + bv1;
        }
    }
}

// ---------------- tf32 tensor GEMM: gamma = exp(-relu(delta@Wgh + b)) --------
__global__ void __launch_bounds__(256, 2) k_gamma(const float* __restrict__ Wgh,
                                                  const float* __restrict__ bgh) {
    extern __shared__ float sm[];
    float* sA = sm;
    float* sB = sm + 2*128*PAD_A;
    int ct = blockIdx.x, i = blockIdx.y, tid = threadIdx.x;
    int lane = tid & 31, warp = tid >> 5;
    int wm = warp & 1, wn = warp >> 1;

    auto loadA = [&](int ck, int buf) {
        int k0 = ck*32;
#pragma unroll
        for (int v = 0; v < 4; v++) {
            int idx = tid + v*256;
            int b = idx >> 3;
            int kq = (idx & 7) * 4;
            cp16(sA + buf*128*PAD_A + b*PAD_A + kq,
                 g_deltaS + ((size_t)i*Bdim + b)*Hdim + k0 + kq);
        }
    };
    auto loadB = [&](int ck, int buf) {
        int k0 = ck*32;
#pragma unroll
        for (int v = 0; v < 4; v++) {
            int idx = tid + v*256;
            int k = idx >> 5;
            int q = (idx & 31) * 4;
            cp16(sB + buf*32*PAD_B + k*PAD_B + q,
                 Wgh + (size_t)(k0 + k)*Hdim + ct*128 + q);
        }
    };

    float c[4][4][4] = {};
    loadA(0, 0); loadB(0, 0); CP_COMMIT;
    for (int ck = 0; ck < 16; ck++) {
        if (ck < 15) { loadA(ck+1, (ck+1)&1); loadB(ck+1, (ck+1)&1); CP_COMMIT; CP_WAIT1; }
        else         { CP_WAIT0; }
        __syncthreads();
        const float* A = sA + (ck&1)*128*PAD_A;
        const float* B = sB + (ck&1)*32*PAD_B;
#pragma unroll
        for (int ks = 0; ks < 4; ks++) {
            unsigned af[4][4], bf[4][2];
#pragma unroll
            for (int mi = 0; mi < 4; mi++) {
                int r  = wm*64 + mi*16 + (lane >> 2);
                int cc = ks*8 + (lane & 3);
                af[mi][0] = f2tf32(A[r*PAD_A + cc]);
                af[mi][1] = f2tf32(A[(r+8)*PAD_A + cc]);
                af[mi][2] = f2tf32(A[r*PAD_A + cc + 4]);
                af[mi][3] = f2tf32(A[(r+8)*PAD_A + cc + 4]);
            }
#pragma unroll
            for (int ni = 0; ni < 4; ni++) {
                int n  = wn*32 + ni*8 + (lane >> 2);
                int kk = ks*8 + (lane & 3);
                bf[ni][0] = f2tf32(B[kk*PAD_B + n]);
                bf[ni][1] = f2tf32(B[(kk+4)*PAD_B + n]);
            }
#pragma unroll
            for (int mi = 0; mi < 4; mi++)
#pragma unroll
                for (int ni = 0; ni < 4; ni++)
                    mma_tf32(c[mi][ni], af[mi][0], af[mi][1], af[mi][2], af[mi][3],
                             bf[ni][0], bf[ni][1]);
        }
        __syncthreads();
    }
#pragma unroll
    for (int mi = 0; mi < 4; mi++) {
        int r0 = wm*64 + mi*16 + (lane >> 2);
#pragma unroll
        for (int ni = 0; ni < 4; ni++) {
            int col0 = ct*128 + wn*32 + ni*8 + (lane & 3)*2;
            float bv0 = __ldg(&bgh[col0]);
            float bv1 = __ldg(&bgh[col0 + 1]);
            float* d0 = g_gamma + (size_t)i*(Hdim*Bdim) + (size_t)col0*Bdim;
            float* d1 = d0 + Bdim;
            d0[r0]     = __expf(-fmaxf(0.f, c[mi][ni][0] + bv0));
            d1[r0]     = __expf(-fmaxf(0.f, c[mi][ni][1] + bv1));
            d0[r0 + 8] = __expf(-fmaxf(0.f, c[mi][ni][2] + bv0));
            d1[r0 + 8] = __expf(-fmaxf(0.f, c[mi][ni][3] + bv1));
        }
    }
}

// ============ persistent recurrence: tensor-core, batch-group split ==========
// 128 CTAs = 4 batch groups (32 batches) x 32 col groups.
// Phase1: zr cols cg*32..+31 (K=512).  Phase2: cand cols cg*16..+15 (K=512).
// XOR swizzles (bank-conflict-free transposed A-frag + B-frag loads):
#define SWH(k,b) ((k)*32 + ((b) ^ (((k)&3)<<3)))
#define SW3(k,n) ((k)*16 + ((n) ^ (((k)&2)<<2)))
#define OFF_H    0
#define OFF_WZR  16384
#define OFF_W3   32768
#define OFF_PART 40960
#define MAIN_SM_FLOATS 49408   // 193 KB

__global__ void __launch_bounds__(512, 1) k_main(const float* __restrict__ Wh) {
    extern __shared__ float sm[];
    float* smH   = sm + OFF_H;     // [512][32] swizzled (h_s / rh batch slice)
    float* sWzr  = sm + OFF_WZR;   // [512][32] swizzled
    float* sW3   = sm + OFF_W3;    // [512][16] swizzled
    float* sPart = sm + OFF_PART;  // K-group partials

    const int c   = blockIdx.x;
    const int tid = threadIdx.x;
    const int bg  = c & 3;
    const int cg  = c >> 2;
    const int lane = tid & 31, warp = tid >> 5;
    const int kg = warp >> 1, mh = warp & 1;
    const int r = lane >> 2, q = lane & 3;

    // one-time weight slices
    for (int f = tid; f < 4096; f += 512) {          // Wh_zr: 512x32
        int k = f >> 3, n = (f & 7) * 4;
        cp16(&sWzr[SWH(k, n)], &Wh[(size_t)k*1536 + cg*32 + n]);
    }
    for (int f = tid; f < 2048; f += 512) {          // Wh3: 512x16
        int k = f >> 2, n = (f & 3) * 4;
        cp16(&sW3[SW3(k, n)], &Wh[(size_t)k*1536 + 1024 + cg*16 + n]);
    }
    CP_COMMIT; CP_WAIT0;
    __syncthreads();

    unsigned epoch = 0;

    for (int i = 0; i < Ldim; i++) {
        // ---------- stage h_scaled batch slice ----------
#pragma unroll
        for (int v = 0; v < 8; v++) {
            int f = tid + v*512;               // 0..4095 (512k x 32b /4)
            int k = f >> 3, nb = (f & 7) * 4;
            cp16(&smH[SWH(k, nb)], &g_hsT[k*128 + bg*32 + nb]);
        }
        CP_COMMIT; CP_WAIT0;
        __syncthreads();

        // ---------- phase1 mma: C[32b x 32col], warp = (kg K-slice 64, mh rows 16)
        {
            float acc[4][4] = {};
#pragma unroll
            for (int ks = 0; ks < 8; ks++) {
                int ka = kg*64 + ks*8 + q;
                int kb = ka + 4;
                int row = mh*16 + r;
                float a0f = smH[SWH(ka, row)];
                float a1f = smH[SWH(ka, row + 8)];
                float a2f = smH[SWH(kb, row)];
                float a3f = smH[SWH(kb, row + 8)];
                unsigned ah0 = f2tf32(a0f), ah1 = f2tf32(a1f);
                unsigned ah2 = f2tf32(a2f), ah3 = f2tf32(a3f);
                unsigned al0 = f2tf32(a0f - __uint_as_float(ah0));
                unsigned al1 = f2tf32(a1f - __uint_as_float(ah1));
                unsigned al2 = f2tf32(a2f - __uint_as_float(ah2));
                unsigned al3 = f2tf32(a3f - __uint_as_float(ah3));
#pragma unroll
                for (int nt = 0; nt < 4; nt++) {
                    int n = nt*8 + r;
                    float b0f = sWzr[SWH(ka, n)];
                    float b1f = sWzr[SWH(kb, n)];
                    unsigned bh0 = f2tf32(b0f), bh1 = f2tf32(b1f);
                    unsigned bl0 = f2tf32(b0f - __uint_as_float(bh0));
                    unsigned bl1 = f2tf32(b1f - __uint_as_float(bh1));
                    mma_tf32(acc[nt], ah0, ah1, ah2, ah3, bh0, bh1);
                    mma_tf32(acc[nt], al0, al1, al2, al3, bh0, bh1);
                    mma_tf32(acc[nt], ah0, ah1, ah2, ah3, bl0, bl1);
                }
            }
            // write K-group partials (stride 33)
            float* P = sPart + kg*1056;
            int row = mh*16 + r;
#pragma unroll
            for (int nt = 0; nt < 4; nt++) {
                int col = nt*8 + 2*q;
                P[row*33 + col]       = acc[nt][0];
                P[row*33 + col + 1]   = acc[nt][1];
                P[(row+8)*33 + col]   = acc[nt][2];
                P[(row+8)*33 + col+1] = acc[nt][3];
            }
        }
        __syncthreads();
        // reduce 8 partials + activation (col = warp (+16), b = lane)
#pragma unroll
        for (int o = 0; o < 2; o++) {
            int col = warp + o*16;
            int b   = lane;
            float s = 0.f;
#pragma unroll
            for (int g2 = 0; g2 < 8; g2++)
                s += sPart[g2*1056 + b*33 + col];
            int zrcol = cg*32 + col;
            s += __ldg(&g_preZ[(size_t)i*131072 + (size_t)zrcol*128 + bg*32 + b]);
            float sg = 1.f / (1.f + __expf(-s));
            if (zrcol < 512) {
                g_zT[zrcol*128 + bg*32 + b] = sg;
            } else {
                int hc = zrcol - 512;
                g_rhT[hc*128 + bg*32 + b] = sg * smH[SWH(hc, b)];
            }
        }
        bg_barrier(bg, epoch);

        // ---------- stage rh batch slice ----------
#pragma unroll
        for (int v = 0; v < 8; v++) {
            int f = tid + v*512;
            int k = f >> 3, nb = (f & 7) * 4;
            cp16(&smH[SWH(k, nb)], &g_rhT[k*128 + bg*32 + nb]);
        }
        CP_COMMIT; CP_WAIT0;
        __syncthreads();

        // ---------- phase2 mma: C[32b x 16col] ----------
        {
            float acc[2][4] = {};
#pragma unroll
            for (int ks = 0; ks < 8; ks++) {
                int ka = kg*64 + ks*8 + q;
                int kb = ka + 4;
                int row = mh*16 + r;
                float a0f = smH[SWH(ka, row)];
                float a1f = smH[SWH(ka, row + 8)];
                float a2f = smH[SWH(kb, row)];
                float a3f = smH[SWH(kb, row + 8)];
                unsigned ah0 = f2tf32(a0f), ah1 = f2tf32(a1f);
                unsigned ah2 = f2tf32(a2f), ah3 = f2tf32(a3f);
                unsigned al0 = f2tf32(a0f - __uint_as_float(ah0));
                unsigned al1 = f2tf32(a1f - __uint_as_float(ah1));
                unsigned al2 = f2tf32(a2f - __uint_as_float(ah2));
                unsigned al3 = f2tf32(a3f - __uint_as_float(ah3));
#pragma unroll
                for (int nt = 0; nt < 2; nt++) {
                    int n = nt*8 + r;
                    float b0f = sW3[SW3(ka, n)];
                    float b1f = sW3[SW3(kb, n)];
                    unsigned bh0 = f2tf32(b0f), bh1 = f2tf32(b1f);
                    unsigned bl0 = f2tf32(b0f - __uint_as_float(bh0));
                    unsigned bl1 = f2tf32(b1f - __uint_as_float(bh1));
                    mma_tf32(acc[nt], ah0, ah1, ah2, ah3, bh0, bh1);
                    mma_tf32(acc[nt], al0, al1, al2, al3, bh0, bh1);
                    mma_tf32(acc[nt], ah0, ah1, ah2, ah3, bl0, bl1);
                }
            }
            float* P = sPart + kg*544;
            int row = mh*16 + r;
#pragma unroll
            for (int nt = 0; nt < 2; nt++) {
                int col = nt*8 + 2*q;
                P[row*17 + col]       = acc[nt][0];
                P[row*17 + col + 1]   = acc[nt][1];
                P[(row+8)*17 + col]   = acc[nt][2];
                P[(row+8)*17 + col+1] = acc[nt][3];
            }
        }
        __syncthreads();
        // reduce + h update (col = warp 0..15, b = lane)
        {
            int col = warp;
            int b   = lane;
            float s = 0.f;
#pragma unroll
            for (int g2 = 0; g2 < 8; g2++)
                s += sPart[g2*544 + b*17 + col];
            int colg = cg*16 + col;
            int gi   = colg*128 + bg*32 + b;
            float ht = tanhf(s + __ldg(&g_preC[(size_t)i*65536 + gi]));
            float z  = __ldcg(&g_zT[gi]);
            float hs = __ldcg(&g_hsT[gi]);
            float hn = (1.f - z)*hs + z*ht;
            g_hseq[(size_t)i*65536 + gi] = hn;
            if (i + 1 < Ldim)
                g_hsT[gi] = hn * __ldg(&g_gamma[(size_t)(i+1)*65536 + gi]);
        }
        bg_barrier(bg, epoch);
    }
}

// ---------------- tf32 output GEMM: out = h_seq @ W_out + b_out --------------
// grid (2, 256): 128-col tile, i. 256 thr (8 warps 2x4). A = hseq^T via swizzle.
#define OUT_SMEM (2*(4096+4096)*4)
__global__ void __launch_bounds__(256, 2) k_out(const float* __restrict__ Wout,
                                                const float* __restrict__ bout,
                                                float* __restrict__ out) {
    extern __shared__ float sm[];
    float* sA = sm;            // 2 x [32k][128b] swizzled
    float* sB = sm + 8192;     // 2 x [32k][128n] swizzled
    int ct = blockIdx.x, i = blockIdx.y, tid = threadIdx.x;
    int lane = tid & 31, warp = tid >> 5;
    int wm = warp & 1, wn = warp >> 1;

    auto loadA = [&](int ck, int buf) {
#pragma unroll
        for (int v = 0; v < 4; v++) {
            int f = tid + v*256;           // 0..1023
            int k = f >> 5, nb = (f & 31) * 4;
            cp16(&sA[buf*4096 + k*128 + (nb ^ ((k & 3) << 3))],
                 &g_hseq[(size_t)i*65536 + (size_t)(ck*32 + k)*128 + nb]);
        }
    };
    auto loadB = [&](int ck, int buf) {
#pragma unroll
        for (int v = 0; v < 4; v++) {
            int f = tid + v*256;
            int k = f >> 5, nb = (f & 31) * 4;
            cp16(&sB[buf*4096 + k*128 + (nb ^ ((k & 3) << 3))],
                 &Wout[(size_t)(ck*32 + k)*OUTdim + ct*128 + nb]);
        }
    };

    float c[4][4][4] = {};
    loadA(0, 0); loadB(0, 0); CP_COMMIT;
    for (int ck = 0; ck < 16; ck++) {
        if (ck < 15) { loadA(ck+1, (ck+1)&1); loadB(ck+1, (ck+1)&1); CP_COMMIT; CP_WAIT1; }
        else         { CP_WAIT0; }
        __syncthreads();
        const float* A = sA + (ck&1)*4096;
        const float* B = sB + (ck&1)*4096;
#pragma unroll
        for (int ks = 0; ks < 4; ks++) {
            int ka = ks*8 + (lane & 3);
            int kb = ka + 4;
            unsigned af[4][4], bf[4][2];
#pragma unroll
            for (int mi = 0; mi < 4; mi++) {
                int b0 = wm*64 + mi*16 + (lane >> 2);
                af[mi][0] = f2tf32(A[ka*128 + (b0 ^ ((ka & 3) << 3))]);
                af[mi][1] = f2tf32(A[ka*128 + ((b0+8) ^ ((ka & 3) << 3))]);
                af[mi][2] = f2tf32(A[kb*128 + (b0 ^ ((kb & 3) << 3))]);
                af[mi][3] = f2tf32(A[kb*128 + ((b0+8) ^ ((kb & 3) << 3))]);
            }
#pragma unroll
            for (int ni = 0; ni < 4; ni++) {
                int n = wn*32 + ni*8 + (lane >> 2);
                bf[ni][0] = f2tf32(B[ka*128 + (n ^ ((ka & 3) << 3))]);
                bf[ni][1] = f2tf32(B[kb*128 + (n ^ ((kb & 3) << 3))]);
            }
#pragma unroll
            for (int mi = 0; mi < 4; mi++)
#pragma unroll
                for (int ni = 0; ni < 4; ni++)
                    mma_tf32(c[mi][ni], af[mi][0], af[mi][1], af[mi][2], af[mi][3],
                             bf[ni][0], bf[ni][1]);
        }
        __syncthreads();
    }
#pragma unroll
    for (int mi = 0; mi < 4; mi++) {
        int r0 = wm*64 + mi*16 + (lane >> 2);
#pragma unroll
        for (int ni = 0; ni < 4; ni++) {
            int o0 = ct*128 + wn*32 + ni*8 + (lane & 3)*2;
            float bv0 = __ldg(&bout[o0]);
            float bv1 = __ldg(&bout[o0 + 1]);
            out[((size_t)r0*Ldim + i)*OUTdim + o0]         = c[mi][ni][0] + bv0;
            out[((size_t)r0*Ldim + i)*OUTdim + o0 + 1]     = c[mi][ni][1] + bv1;
            out[((size_t)(r0+8)*Ldim + i)*OUTdim + o0]     = c[mi][ni][2] + bv0;
            out[((size_t)(r0+8)*Ldim + i)*OUTdim + o0 + 1] = c[mi][ni][3] + bv1;
        }
    }
}

// ---------------- launch ------------------------------------------------------
extern "C" void kernel_launch(void* const* d_in, const int* in_sizes, int n_in,
                              void* d_out, int out_size) {
    const float* C    = (const float*)d_in[0];
    const float* t    = (const float*)d_in[1];
    const int*   mask = (const int*)  d_in[2];
    const float* Wx   = (const float*)d_in[3];
    const float* Wh   = (const float*)d_in[4];
    const float* Wm   = (const float*)d_in[5];
    const float* bvec = (const float*)d_in[6];
    const float* wgx  = (const float*)d_in[7];
    const float* bgx  = (const float*)d_in[8];
    const float* Wgh  = (const float*)d_in[9];
    const float* bgh  = (const float*)d_in[10];
    const float* Wout = (const float*)d_in[11];
    const float* bout = (const float*)d_in[12];
    float* out = (float*)d_out;

    cudaFuncSetAttribute(k_main, cudaFuncAttributeMaxDynamicSharedMemorySize,
                         MAIN_SM_FLOATS * 4);
    cudaFuncSetAttribute(k_pre, cudaFuncAttributeMaxDynamicSharedMemorySize, PRE_SMEM);
    cudaFuncSetAttribute(k_gamma, cudaFuncAttributeMaxDynamicSharedMemorySize, PRE_SMEM);
    cudaFuncSetAttribute(k_out, cudaFuncAttributeMaxDynamicSharedMemorySize, OUT_SMEM);

    k_maskf<<<(Bdim*Ldim*Hdim)/1024, 1024>>>(mask);
    k_setup<<<Bdim, Hdim>>>(C, t, mask);
    k_scan<<<128, 512>>>(C, wgx, bgx);
    k_pre<<<dim3(12, Ldim), 256, PRE_SMEM>>>(Wx, Wm, bvec);
    k_gamma<<<dim3(4, Ldim), 256, PRE_SMEM>>>(Wgh, bgh);
    k_main<<<NCTA, 512, MAIN_SM_FLOATS * 4>>>(Wh);
    k_out<<<dim3(2, Ldim), 256, OUT_SMEM>>>(Wout, bout, out);
}